// round 15
// baseline (speedup 1.0000x reference)
#include <cuda_runtime.h>
#include <cuda_fp16.h>
#include <cstdint>

// ---------------- problem constants ----------------
#define B_    32
#define CIN   128
#define COUT  256
#define HW    3136
#define HDIM  56
#define EXP_  4
#define RDIM  16
#define TILES 784          // 28x28 Winograd F(2x2,3x3) tiles
#define TT    64           // tiles per gemm CTA
#define TTILES 13          // ceil(784/64)

// ---------------- device scratch ----------------
__device__ float g_routing[B_ * EXP_];
__device__ float g_gappart[B_ * 28 * CIN];   // per-tile-row GAP partials
// U = GgG^T fp16: [b][comp16][co256][ci128]
__device__ __align__(16) __half g_u[(size_t)B_ * 16 * COUT * CIN];
// V = B^TdB fp16: [b][comp16][tile784][ci128]
__device__ __align__(16) __half g_v[(size_t)B_ * 16 * TILES * CIN];

// ---------------- helpers ----------------
__device__ __forceinline__ uint32_t smem_u32(const void* p) {
    uint32_t a;
    asm("{ .reg .u64 t; cvta.to.shared.u64 t, %1; cvt.u32.u64 %0, t; }" : "=r"(a) : "l"(p));
    return a;
}
__device__ __forceinline__ void cp16(uint32_t dst, const void* src, int sz) {
    asm volatile("cp.async.cg.shared.global [%0], [%1], 16, %2;"
                 :: "r"(dst), "l"(src), "r"(sz) : "memory");
}
#define CP_COMMIT() asm volatile("cp.async.commit_group;" ::: "memory")
#define CP_WAIT(n)  asm volatile("cp.async.wait_group %0;" :: "n"(n) : "memory")

#define LDSM4(r, a)                                                              \
    asm volatile("ldmatrix.sync.aligned.m8n8.x4.shared.b16 {%0,%1,%2,%3}, [%4];" \
        : "=r"((r)[0]), "=r"((r)[1]), "=r"((r)[2]), "=r"((r)[3]) : "r"(a))

__device__ __forceinline__ void mma16816(float* c, const uint32_t* a,
                                         uint32_t b0, uint32_t b1) {
    asm volatile(
        "mma.sync.aligned.m16n8k16.row.col.f32.f16.f16.f32 "
        "{%0,%1,%2,%3}, {%4,%5,%6,%7}, {%8,%9}, {%0,%1,%2,%3};"
        : "+f"(c[0]), "+f"(c[1]), "+f"(c[2]), "+f"(c[3])
        : "r"(a[0]), "r"(a[1]), "r"(a[2]), "r"(a[3]), "r"(b0), "r"(b1));
}

// ---------------------------------------------------------------------------
// Kernel A: Winograd input transform V = B^T d B from fp32 x directly,
// fused GAP partials.  grid (28 tile-rows, 32 b), 256 threads.
// Smem: 4 padded rows x 128 ci x 59 fp32 (118KB).  Single fp16 rounding.
// ---------------------------------------------------------------------------
#define VT_SMEM (4 * 128 * 59 * 4)   // 120832
__global__ void vtrans_kernel(const float* __restrict__ x) {
    extern __shared__ float slab[];
    int tr = blockIdx.x, b = blockIdx.y;
    int tid = threadIdx.x;

    // ---- fill: slab[r][ci][cc], cc 0..57 are padded cols (-1..56)
    #pragma unroll
    for (int j = 0; j < 2; j++) {
        int pair = tid * 2 + j;              // 0..511
        int r = pair >> 7, ci = pair & 127;
        int orow = 2 * tr + r - 1;
        float* dst = slab + (r * 128 + ci) * 59;
        if ((unsigned)orow > 55u) {
            for (int c = 0; c < 58; c++) dst[c] = 0.f;
        } else {
            const float* src = x + ((size_t)(b * CIN + ci)) * HW + orow * 56;
            dst[0] = 0.f;
            for (int c = 0; c < 56; c++) dst[c + 1] = src[c];
            dst[57] = 0.f;
        }
    }
    __syncthreads();

    // ---- fused GAP partial: rows r=1,2 are orig rows 2tr, 2tr+1 (each once)
    if (tid < 128) {
        float s = 0.f;
        const float* p1 = slab + (1 * 128 + tid) * 59;
        const float* p2 = slab + (2 * 128 + tid) * 59;
        #pragma unroll 8
        for (int c = 1; c <= 56; c++) s += p1[c] + p2[c];
        g_gappart[(b * 28 + tr) * 128 + tid] = s;
    }

    // ---- transform: 14 (tc, ci) items per thread
    #pragma unroll
    for (int it = 0; it < 14; it++) {
        int item = it * 256 + tid;
        int ci = item & 127, tc = item >> 7;        // tc 0..27
        float d[4][4];
        #pragma unroll
        for (int r = 0; r < 4; r++) {
            const float* row = slab + (r * 128 + ci) * 59 + 2 * tc;
            #pragma unroll
            for (int c = 0; c < 4; c++) d[r][c] = row[c];
        }
        float e[4][4];
        #pragma unroll
        for (int c = 0; c < 4; c++) {
            e[0][c] = d[0][c] - d[2][c];
            e[1][c] = d[1][c] + d[2][c];
            e[2][c] = d[2][c] - d[1][c];
            e[3][c] = d[1][c] - d[3][c];
        }
        int t = tr * 28 + tc;
        size_t base = ((size_t)(b * 16) * TILES + t) * CIN + ci;
        size_t cstep = (size_t)TILES * CIN;
        #pragma unroll
        for (int u = 0; u < 4; u++) {
            g_v[base + (u * 4 + 0) * cstep] = __float2half_rn(e[u][0] - e[u][2]);
            g_v[base + (u * 4 + 1) * cstep] = __float2half_rn(e[u][1] + e[u][2]);
            g_v[base + (u * 4 + 2) * cstep] = __float2half_rn(e[u][2] - e[u][1]);
            g_v[base + (u * 4 + 3) * cstep] = __float2half_rn(e[u][1] - e[u][3]);
        }
    }
}

// ---------------------------------------------------------------------------
// Kernel B: router MLP + softmax.  grid 32, 32 threads.
// ---------------------------------------------------------------------------
__global__ void router_kernel(const float* __restrict__ w1, const float* __restrict__ b1,
                              const float* __restrict__ w2, const float* __restrict__ b2) {
    int b = blockIdx.x, t = threadIdx.x;
    __shared__ float gap[CIN], h[RDIM], lg[EXP_];
    const float invHW = 1.0f / (float)HW;
    // reduce 28 partials per channel
    for (int c = t; c < CIN; c += 32) {
        float s = 0.f;
        #pragma unroll 4
        for (int trr = 0; trr < 28; trr++)
            s += g_gappart[(b * 28 + trr) * 128 + c];
        gap[c] = s * invHW;
    }
    __syncwarp();
    if (t < RDIM) {
        float a = b1[t];
        const float* wr = w1 + t * CIN;
        #pragma unroll 8
        for (int c = 0; c < CIN; c++) a = fmaf(wr[c], gap[c], a);
        h[t] = fmaxf(a, 0.f);
    }
    __syncwarp();
    if (t < EXP_) {
        float a = b2[t];
        #pragma unroll
        for (int r = 0; r < RDIM; r++) a = fmaf(w2[t * RDIM + r], h[r], a);
        lg[t] = a;
    }
    __syncwarp();
    if (t == 0) {
        float m = fmaxf(fmaxf(lg[0], lg[1]), fmaxf(lg[2], lg[3]));
        float e[EXP_], ss = 0.f;
        #pragma unroll
        for (int i = 0; i < EXP_; i++) { e[i] = expf((lg[i] - m) * (1.0f / 30.0f)); ss += e[i]; }
        float inv = 1.0f / ss;
        #pragma unroll
        for (int i = 0; i < EXP_; i++) g_routing[b * EXP_ + i] = e[i] * inv;
    }
}

// ---------------------------------------------------------------------------
// Kernel C: mix experts + U = G g G^T -> fp16, half2 stores.
// grid (256 co, 4 bg), 64 threads (2 ci each), 8 samples per block.
// ---------------------------------------------------------------------------
__global__ void umix_kernel(const float* __restrict__ convs) {
    int co = blockIdx.x, bg = blockIdx.y;
    int tid = threadIdx.x;                 // 0..63, ci pair = 2*tid
    __shared__ float se[EXP_][CIN * 9];
    for (int e = 0; e < EXP_; e++) {
        const float* src = convs + ((size_t)(e * COUT + co)) * (CIN * 9);
        for (int i = tid; i < CIN * 9; i += 64) se[e][i] = src[i];
    }
    __syncthreads();

    for (int b = bg * 8; b < bg * 8 + 8; b++) {
        float r0 = g_routing[b * EXP_ + 0], r1 = g_routing[b * EXP_ + 1];
        float r2 = g_routing[b * EXP_ + 2], r3 = g_routing[b * EXP_ + 3];
        float m[2][9];
        #pragma unroll
        for (int p = 0; p < 2; p++) {
            int ci = 2 * tid + p;
            #pragma unroll
            for (int k = 0; k < 9; k++) {
                int j = ci * 9 + k;
                m[p][k] = fmaf(r0, se[0][j], fmaf(r1, se[1][j], fmaf(r2, se[2][j], r3 * se[3][j])));
            }
        }
        float q[2][4][3];
        #pragma unroll
        for (int p = 0; p < 2; p++)
            #pragma unroll
            for (int c = 0; c < 3; c++) {
                q[p][0][c] = m[p][c];
                q[p][1][c] = 0.5f * (m[p][c] + m[p][3 + c] + m[p][6 + c]);
                q[p][2][c] = 0.5f * (m[p][c] - m[p][3 + c] + m[p][6 + c]);
                q[p][3][c] = m[p][6 + c];
            }
        #pragma unroll
        for (int u = 0; u < 4; u++) {
            float U[2][4];
            #pragma unroll
            for (int p = 0; p < 2; p++) {
                U[p][0] = q[p][u][0];
                U[p][1] = 0.5f * (q[p][u][0] + q[p][u][1] + q[p][u][2]);
                U[p][2] = 0.5f * (q[p][u][0] - q[p][u][1] + q[p][u][2]);
                U[p][3] = q[p][u][2];
            }
            size_t base = ((size_t)(b * 16 + u * 4) * COUT + co) * CIN + 2 * tid;
            size_t cstep = (size_t)COUT * CIN;
            #pragma unroll
            for (int v = 0; v < 4; v++) {
                __half2 hv = __floats2half2_rn(U[0][v], U[1][v]);
                *(__half2*)(g_u + base + v * cstep) = hv;
            }
        }
    }
}

// ---------------------------------------------------------------------------
// Kernel D: Winograd GEMM + output transform (unchanged from R12).
// grid (13, 2, 32), 512 threads (16 warps, 4x4).
// ---------------------------------------------------------------------------
#define STAGE_B 49152                      // 16KB B + 32KB A
#define SMEM_DYN (3 * STAGE_B + 1024)      // 148480

__global__ __launch_bounds__(512, 1)
void wgemm_kernel(float* __restrict__ out) {
    extern __shared__ char dyn[];
    uint32_t sb = smem_u32(dyn);
    uint32_t ab = (sb + 1023u) & ~1023u;

    const int tid = threadIdx.x, w = tid >> 5, lane = tid & 31;
    const int wm = w & 3, wn = w >> 2;
    const int ttile = blockIdx.x, cotile = blockIdx.y, b = blockIdx.z;
    const int t0 = ttile * TT;

    auto load_comp = [&](int c) {
        uint32_t stg = ab + (uint32_t)(c % 3) * STAGE_B;
        const __half* vslab = g_v + ((size_t)(b * 16 + c)) * TILES * CIN;
        #pragma unroll
        for (int j = 0; j < 2; j++) {
            int idx = tid + j * 512;
            int row = idx >> 4, u = idx & 15;
            int t = t0 + row;
            bool v = t < TILES;
            uint32_t so = stg + row * 256 + ((u & 8) << 4) + (((u & 7) ^ (row & 7)) << 4);
            cp16(so, vslab + (size_t)(v ? t : 0) * CIN + u * 8, v ? 16 : 0);
        }
        const __half* uslab = g_u + ((size_t)(b * 16 + c) * COUT + cotile * 128) * CIN;
        uint32_t abase = stg + 16384;
        #pragma unroll
        for (int j = 0; j < 4; j++) {
            int idx = tid + j * 512;
            int row = idx >> 4, u = idx & 15;
            uint32_t so = abase + row * 256 + ((u & 8) << 4) + (((u & 7) ^ (row & 7)) << 4);
            cp16(so, uslab + (size_t)row * CIN + u * 8, 16);
        }
    };

    const int aR0  = wm * 32 + (lane & 15);
    const int aSel = lane >> 4;
    const int jlo  = (lane >> 3) & 1;
    const int rowin = ((lane >> 4) << 3) + (lane & 7);
    const int brow = wn * 16 + rowin;
    const int grp = lane >> 2, tg = lane & 3;

    static const float KA[2][4] = {{1.f, 1.f, 1.f, 0.f}, {0.f, 1.f, -1.f, -1.f}};

    float oacc[2][2][4][4];
    #pragma unroll
    for (int a0 = 0; a0 < 2; a0++)
        #pragma unroll
        for (int a1 = 0; a1 < 2; a1++)
            #pragma unroll
            for (int a2 = 0; a2 < 4; a2++)
                #pragma unroll
                for (int a3 = 0; a3 < 4; a3++) oacc[a0][a1][a2][a3] = 0.f;

    load_comp(0);
    CP_COMMIT();
    load_comp(1);
    CP_COMMIT();

    #pragma unroll
    for (int c = 0; c < 16; c++) {
        if (c == 15) { CP_WAIT(0); } else { CP_WAIT(1); }
        __syncthreads();
        if (c + 2 < 16) { load_comp(c + 2); CP_COMMIT(); }

        uint32_t stg = ab + (uint32_t)(c % 3) * STAGE_B;
        uint32_t Bb = stg, Ab = stg + 16384;

        float macc[2][2][4];
        #pragma unroll
        for (int mf = 0; mf < 2; mf++)
            #pragma unroll
            for (int nf = 0; nf < 2; nf++)
                #pragma unroll
                for (int u = 0; u < 4; u++) macc[mf][nf][u] = 0.f;

        #pragma unroll
        for (int s = 0; s < 8; s++) {
            uint32_t ah[2][4], bh[4];
            #pragma unroll
            for (int mf = 0; mf < 2; mf++) {
                int row = aR0 + mf * 16;
                int u = (s << 1) | aSel;
                uint32_t off = row * 256 + ((u & 8) << 4) + (((u & 7) ^ (row & 7)) << 4);
                LDSM4(ah[mf], Ab + off);
            }
            {
                int u = (s << 1) | jlo;
                uint32_t off = brow * 256 + ((u & 8) << 4) + (((u & 7) ^ (brow & 7)) << 4);
                LDSM4(bh, Bb + off);
            }
            #pragma unroll
            for (int mf = 0; mf < 2; mf++) {
                mma16816(macc[mf][0], ah[mf], bh[0], bh[1]);
                mma16816(macc[mf][1], ah[mf], bh[2], bh[3]);
            }
        }

        const int cu = c >> 2, cv = c & 3;
        #pragma unroll
        for (int i = 0; i < 2; i++)
            #pragma unroll
            for (int j = 0; j < 2; j++) {
                float kc = KA[i][cu] * KA[j][cv];
                if (kc != 0.f) {
                    #pragma unroll
                    for (int mf = 0; mf < 2; mf++)
                        #pragma unroll
                        for (int nf = 0; nf < 2; nf++)
                            #pragma unroll
                            for (int r4 = 0; r4 < 4; r4++)
                                oacc[mf][nf][r4][i * 2 + j] =
                                    fmaf(kc, macc[mf][nf][r4], oacc[mf][nf][r4][i * 2 + j]);
                }
            }
    }

    #pragma unroll
    for (int mf = 0; mf < 2; mf++)
        #pragma unroll
        for (int nf = 0; nf < 2; nf++) {
            int t_a = t0 + wn * 16 + nf * 8 + 2 * tg;
            if (t_a < TILES) {
                int tr = t_a / 28, tc = t_a % 28;
                #pragma unroll
                for (int ch = 0; ch < 2; ch++) {
                    int co = cotile * 128 + wm * 32 + mf * 16 + grp + ch * 8;
                    float* base = out + ((size_t)(b * COUT + co)) * HW;
                    #pragma unroll
                    for (int i = 0; i < 2; i++) {
                        float4 v;
                        v.x = oacc[mf][nf][ch * 2 + 0][i * 2 + 0];
                        v.y = oacc[mf][nf][ch * 2 + 0][i * 2 + 1];
                        v.z = oacc[mf][nf][ch * 2 + 1][i * 2 + 0];
                        v.w = oacc[mf][nf][ch * 2 + 1][i * 2 + 1];
                        *(float4*)(base + (2 * tr + i) * HDIM + 2 * tc) = v;
                    }
                }
            }
        }
}

// ---------------------------------------------------------------------------
extern "C" void kernel_launch(void* const* d_in, const int* in_sizes, int n_in,
                              void* d_out, int out_size) {
    const float* x     = (const float*)d_in[0];
    const float* convs = (const float*)d_in[1];
    const float* w1    = (const float*)d_in[2];
    const float* b1    = (const float*)d_in[3];
    const float* w2    = (const float*)d_in[4];
    const float* b2    = (const float*)d_in[5];
    float* out = (float*)d_out;
    (void)in_sizes; (void)n_in; (void)out_size;

    cudaFuncSetAttribute(vtrans_kernel,
                         cudaFuncAttributeMaxDynamicSharedMemorySize, VT_SMEM);
    cudaFuncSetAttribute(wgemm_kernel,
                         cudaFuncAttributeMaxDynamicSharedMemorySize, SMEM_DYN);

    vtrans_kernel<<<dim3(28, B_), 256, VT_SMEM>>>(x);
    router_kernel<<<B_, 32>>>(w1, b1, w2, b2);
    umix_kernel<<<dim3(COUT, 4), 64>>>(convs);
    wgemm_kernel<<<dim3(TTILES, 2, B_), 512, SMEM_DYN>>>(out);
}